// round 3
// baseline (speedup 1.0000x reference)
#include <cuda_runtime.h>
#include <cuda_bf16.h>

// LSTM: B=65536, T=20, I=36, H=30. Gate order i,f,g,o.
// Output: out[B,T,H] ++ h_n[1,B,H] ++ c_n[1,B,H], fp32.
//
// 2 batches per thread packed into f32x2 lanes -> fma.rn.f32x2 (FFMA2),
// 2x the per-issue FP32 rate of scalar FFMA (rt_SMSP 2 either way).
// Weights duplicated (w,w) in smem, broadcast LDS.128 (2 packed weights).

#define NB   65536
#define NT   20
#define NI   36
#define NH   30
#define G4   120
#define WPAD 32            // packed W_hh rows padded to 32 pairs
#define XPAD 37            // stage pitch (gcd(5,32)=1 -> conflict-free)

#define N_CHUNK 1024       // 65536 / 64 batches per warp
#define GRID    296
#define BLOCK   128

typedef unsigned long long u64;

// smem layout in u64 units
#define OFF_WIHP 0                         // 120*36 = 4320
#define OFF_WHHP 4320                      // 120*32 = 3840
#define OFF_BP   8160                      // 120
#define OFF_STG_U64 8280                   // stage floats start here (byte 66240, 16B aligned)
#define STG_PER_WARP (64 * XPAD)           // 2368 floats per warp
#define SMEM_BYTES (OFF_STG_U64 * 8 + 4 * STG_PER_WARP * 4)   // 104128 B

__device__ __forceinline__ u64 fma2(u64 a, u64 b, u64 c) {
    u64 d;
    asm("fma.rn.f32x2 %0, %1, %2, %3;" : "=l"(d) : "l"(a), "l"(b), "l"(c));
    return d;
}
__device__ __forceinline__ u64 pack2(float lo, float hi) {
    u64 d;
    asm("mov.b64 %0, {%1, %2};" : "=l"(d) : "f"(lo), "f"(hi));
    return d;
}
__device__ __forceinline__ void unpack2(u64 v, float& lo, float& hi) {
    asm("mov.b64 {%0, %1}, %2;" : "=f"(lo), "=f"(hi) : "l"(v));
}

__device__ __forceinline__ float sigmoid_f(float v) {
    return __fdividef(1.0f, 1.0f + __expf(-v));
}
__device__ __forceinline__ float tanh_f(float v) {
    return __fdividef(2.0f, 1.0f + __expf(-2.0f * v)) - 1.0f;
}

__global__ void __launch_bounds__(BLOCK, 2)
lstm_fused(const float* __restrict__ x,
           const float* __restrict__ W_ih,
           const float* __restrict__ W_hh,
           const float* __restrict__ b_ih,
           const float* __restrict__ b_hh,
           float* __restrict__ out) {
    extern __shared__ u64 smu[];
    u64* sWihP = smu + OFF_WIHP;   // [120][36] duplicated pairs
    u64* sWhhP = smu + OFF_WHHP;   // [120][32] duplicated pairs (pad 0)
    u64* sBP   = smu + OFF_BP;     // [120] duplicated (b_ih+b_hh)
    float* stage = (float*)(smu + OFF_STG_U64);

    const int tid  = threadIdx.x;
    const int wid  = tid >> 5;
    const int lane = tid & 31;

    // ---- cooperative packed-weight staging ----
    for (int i = tid; i < G4 * NI; i += BLOCK) {
        float w = W_ih[i];
        sWihP[i] = pack2(w, w);
    }
    for (int i = tid; i < G4 * WPAD; i += BLOCK) {
        int r = i >> 5, c = i & 31;
        float w = (c < NH) ? W_hh[r * NH + c] : 0.0f;
        sWhhP[i] = pack2(w, w);
    }
    if (tid < G4) {
        float b = b_ih[tid] + b_hh[tid];
        sBP[tid] = pack2(b, b);
    }
    __syncthreads();

    const int C = wid * GRID + blockIdx.x;   // balanced warp->chunk map
    if (C >= N_CHUNK) return;

    const int bbase = C * 64;
    const int b0 = bbase + lane;
    const int b1 = b0 + 32;

    float* wbuf = stage + wid * STG_PER_WARP;   // 64 x 37 floats, warp-private

    u64 hp[WPAD];        // packed h (batch0,batch1); pad entries stay 0
    float c0[NH], c1[NH];  // cell state, local mem (dynamic hh index)
#pragma unroll
    for (int j = 0; j < WPAD; j++) hp[j] = 0ull;
#pragma unroll
    for (int j = 0; j < NH; j++) { c0[j] = 0.0f; c1[j] = 0.0f; }

    const float4* __restrict__ xg = reinterpret_cast<const float4*>(x);

    for (int t = 0; t < NT; t++) {
        // ---- coalesced x stage: 64 rows x 36 floats -> wbuf ----
#pragma unroll
        for (int k = 0; k < 18; k++) {
            int i4 = lane + 32 * k;          // 64 rows * 9 float4
            int r  = i4 / 9;
            int c4 = i4 - r * 9;
            float4 v = xg[(size_t)(bbase + r) * (NT * NI / 4) + t * (NI / 4) + c4];
            float* d = wbuf + r * XPAD + c4 * 4;
            d[0] = v.x; d[1] = v.y; d[2] = v.z; d[3] = v.w;
        }
        __syncwarp();

        // pack this thread's two x rows (lane-private rows lane, lane+32)
        u64 xrp[NI];
#pragma unroll
        for (int j = 0; j < NI; j++)
            xrp[j] = pack2(wbuf[lane * XPAD + j], wbuf[(lane + 32) * XPAD + j]);

#pragma unroll 1
        for (int hh = 0; hh < NH; hh++) {
            u64 a0 = sBP[hh];
            u64 a1 = sBP[NH + hh];
            u64 a2 = sBP[2 * NH + hh];
            u64 a3 = sBP[3 * NH + hh];

            const u64* w0 = sWihP + (0 * NH + hh) * NI;
            const u64* w1 = sWihP + (1 * NH + hh) * NI;
            const u64* w2 = sWihP + (2 * NH + hh) * NI;
            const u64* w3 = sWihP + (3 * NH + hh) * NI;
#pragma unroll
            for (int q = 0; q < NI; q += 2) {           // broadcast LDS.128 x4
                ulonglong2 p0 = *(const ulonglong2*)(w0 + q);
                ulonglong2 p1 = *(const ulonglong2*)(w1 + q);
                ulonglong2 p2 = *(const ulonglong2*)(w2 + q);
                ulonglong2 p3 = *(const ulonglong2*)(w3 + q);
                u64 xa = xrp[q], xb = xrp[q + 1];
                a0 = fma2(xa, p0.x, a0); a0 = fma2(xb, p0.y, a0);
                a1 = fma2(xa, p1.x, a1); a1 = fma2(xb, p1.y, a1);
                a2 = fma2(xa, p2.x, a2); a2 = fma2(xb, p2.y, a2);
                a3 = fma2(xa, p3.x, a3); a3 = fma2(xb, p3.y, a3);
            }

            const u64* v0 = sWhhP + (0 * NH + hh) * WPAD;
            const u64* v1 = sWhhP + (1 * NH + hh) * WPAD;
            const u64* v2 = sWhhP + (2 * NH + hh) * WPAD;
            const u64* v3 = sWhhP + (3 * NH + hh) * WPAD;
#pragma unroll
            for (int q = 0; q < WPAD; q += 2) {         // pads are 0
                ulonglong2 p0 = *(const ulonglong2*)(v0 + q);
                ulonglong2 p1 = *(const ulonglong2*)(v1 + q);
                ulonglong2 p2 = *(const ulonglong2*)(v2 + q);
                ulonglong2 p3 = *(const ulonglong2*)(v3 + q);
                u64 ha = hp[q], hb = hp[q + 1];
                a0 = fma2(ha, p0.x, a0); a0 = fma2(hb, p0.y, a0);
                a1 = fma2(ha, p1.x, a1); a1 = fma2(hb, p1.y, a1);
                a2 = fma2(ha, p2.x, a2); a2 = fma2(hb, p2.y, a2);
                a3 = fma2(ha, p3.x, a3); a3 = fma2(hb, p3.y, a3);
            }

            float s00, s01, s10, s11, s20, s21, s30, s31;
            unpack2(a0, s00, s01);
            unpack2(a1, s10, s11);
            unpack2(a2, s20, s21);
            unpack2(a3, s30, s31);
            {
                float it = sigmoid_f(s00), ft = sigmoid_f(s10);
                float gt = tanh_f(s20),    ot = sigmoid_f(s30);
                float cn = fmaf(ft, c0[hh], it * gt);
                c0[hh] = cn;
                wbuf[lane * XPAD + hh] = ot * tanh_f(cn);       // lane-private
            }
            {
                float it = sigmoid_f(s01), ft = sigmoid_f(s11);
                float gt = tanh_f(s21),    ot = sigmoid_f(s31);
                float cn = fmaf(ft, c1[hh], it * gt);
                c1[hh] = cn;
                wbuf[(lane + 32) * XPAD + hh] = ot * tanh_f(cn); // lane-private
            }
        }

        // repack h for next step (lane-private rows -> regs)
#pragma unroll
        for (int j = 0; j < NH; j++)
            hp[j] = pack2(wbuf[lane * XPAD + j], wbuf[(lane + 32) * XPAD + j]);
        __syncwarp();

        // ---- coalesced out store from wbuf ----
#pragma unroll
        for (int k = 0; k < 60; k++) {
            int i = lane + 32 * k;           // 64 rows * 30
            int r = i / 30;
            int c = i - r * 30;
            out[(size_t)(bbase + r) * (NT * NH) + t * NH + c] = wbuf[r * XPAD + c];
        }
        __syncwarp();                        // before next t restages x
    }

    // ---- final states ----
    float* hN = out + (size_t)NB * NT * NH;
    float* cN = hN + (size_t)NB * NH;
#pragma unroll
    for (int j = 0; j < NH; j++) {
        float hlo, hhi;
        unpack2(hp[j], hlo, hhi);
        hN[(size_t)b0 * NH + j] = hlo;
        hN[(size_t)b1 * NH + j] = hhi;
        cN[(size_t)b0 * NH + j] = c0[j];
        cN[(size_t)b1 * NH + j] = c1[j];
    }
}

extern "C" void kernel_launch(void* const* d_in, const int* in_sizes, int n_in,
                              void* d_out, int out_size) {
    const float* x    = (const float*)d_in[0];
    const float* W_ih = (const float*)d_in[1];
    const float* W_hh = (const float*)d_in[2];
    const float* b_ih = (const float*)d_in[3];
    const float* b_hh = (const float*)d_in[4];
    float* out = (float*)d_out;

    cudaFuncSetAttribute(lstm_fused,
                         cudaFuncAttributeMaxDynamicSharedMemorySize, SMEM_BYTES);
    lstm_fused<<<GRID, BLOCK, SMEM_BYTES>>>(x, W_ih, W_hh, b_ih, b_hh, out);
}

// round 4
// speedup vs baseline: 1.1395x; 1.1395x over previous
#include <cuda_runtime.h>
#include <cuda_bf16.h>

// LSTM: B=65536, T=20, I=36, H=30. Gate order i,f,g,o.
// Output: out[B,T,H] ++ h_n[1,B,H] ++ c_n[1,B,H], fp32.
//
// j-pair packed FFMA2: accumulator halves hold even/odd j partial sums,
// weights remain in SCALAR smem layout (same LDS traffic as scalar kernel),
// fma.rn.f32x2 halves the FMA-pipe issue count. 2 batches per thread.

#define NB   65536
#define NT   20
#define NI   36
#define NH   30
#define G4   120
#define WPAD 32            // W_hh rows padded to 32 floats
#define XPAD 37            // stage pitch (gcd(5,32)=1 -> conflict-free)

#define N_CHUNK 1024       // 65536 / 64 batches per warp
#define GRID    296
#define BLOCK   128

typedef unsigned long long u64;

// smem float offsets
#define OFF_WIH  0                           // 120*36 = 4320 floats
#define OFF_WHH  (G4 * NI)                   // 120*32 = 3840 floats
#define OFF_B    (OFF_WHH + G4 * WPAD)       // 120 floats
#define OFF_STG  8288                        // 16B aligned
#define STG_PER_WARP (64 * XPAD)             // 2368 floats
#define SMEM_FLOATS (OFF_STG + 4 * STG_PER_WARP)
#define SMEM_BYTES  (SMEM_FLOATS * 4)

__device__ __forceinline__ u64 fma2(u64 a, u64 b, u64 c) {
    u64 d;
    asm("fma.rn.f32x2 %0, %1, %2, %3;" : "=l"(d) : "l"(a), "l"(b), "l"(c));
    return d;
}
__device__ __forceinline__ u64 pack2(float lo, float hi) {
    u64 d;
    asm("mov.b64 %0, {%1, %2};" : "=l"(d) : "f"(lo), "f"(hi));
    return d;
}
__device__ __forceinline__ float sum2(u64 v) {   // lo + hi (reg-pair split is free)
    float lo, hi;
    asm("mov.b64 {%0, %1}, %2;" : "=f"(lo), "=f"(hi) : "l"(v));
    return lo + hi;
}

__device__ __forceinline__ float sigmoid_f(float v) {
    return __fdividef(1.0f, 1.0f + __expf(-v));
}
__device__ __forceinline__ float tanh_f(float v) {
    return __fdividef(2.0f, 1.0f + __expf(-2.0f * v)) - 1.0f;
}

__global__ void __launch_bounds__(BLOCK, 2)
lstm_fused(const float* __restrict__ x,
           const float* __restrict__ W_ih,
           const float* __restrict__ W_hh,
           const float* __restrict__ b_ih,
           const float* __restrict__ b_hh,
           float* __restrict__ out) {
    extern __shared__ float sm[];
    float* sWih = sm + OFF_WIH;     // scalar [120][36]
    float* sWhh = sm + OFF_WHH;     // scalar [120][32], pad = 0
    float* sB   = sm + OFF_B;       // b_ih + b_hh
    float* stage = sm + OFF_STG;

    const int tid  = threadIdx.x;
    const int wid  = tid >> 5;
    const int lane = tid & 31;

    // ---- cooperative weight staging (scalar layout) ----
    for (int i = tid; i < G4 * NI; i += BLOCK) sWih[i] = W_ih[i];
    for (int i = tid; i < G4 * WPAD; i += BLOCK) {
        int r = i >> 5, c = i & 31;
        sWhh[i] = (c < NH) ? W_hh[r * NH + c] : 0.0f;
    }
    if (tid < G4) sB[tid] = b_ih[tid] + b_hh[tid];
    __syncthreads();

    const int C = wid * GRID + blockIdx.x;   // balanced warp->chunk map
    if (C >= N_CHUNK) return;

    const int bbase = C * 64;
    const int b0 = bbase + lane;
    const int b1 = b0 + 32;

    float* wbuf = stage + wid * STG_PER_WARP;   // 64 x 37 floats, warp-private

    u64 hp0[WPAD / 2], hp1[WPAD / 2];   // j-pair packed h per batch (pads 0)
    float c0[NH], c1[NH];               // cell state (local mem, dynamic hh)
#pragma unroll
    for (int j = 0; j < WPAD / 2; j++) { hp0[j] = 0ull; hp1[j] = 0ull; }
#pragma unroll
    for (int j = 0; j < NH; j++) { c0[j] = 0.0f; c1[j] = 0.0f; }

    const float4* __restrict__ xg = reinterpret_cast<const float4*>(x);

    for (int t = 0; t < NT; t++) {
        // ---- coalesced x stage: 64 rows x 36 floats -> wbuf ----
#pragma unroll
        for (int k = 0; k < 18; k++) {
            int i4 = lane + 32 * k;          // 64 rows * 9 float4
            int r  = i4 / 9;
            int c4 = i4 - r * 9;
            float4 v = xg[(size_t)(bbase + r) * (NT * NI / 4) + t * (NI / 4) + c4];
            float* d = wbuf + r * XPAD + c4 * 4;
            d[0] = v.x; d[1] = v.y; d[2] = v.z; d[3] = v.w;
        }
        __syncwarp();

        // j-pair packed x rows for this thread's two batches
        u64 xp0[NI / 2], xp1[NI / 2];
#pragma unroll
        for (int k = 0; k < NI / 2; k++) {
            xp0[k] = pack2(wbuf[lane * XPAD + 2 * k], wbuf[lane * XPAD + 2 * k + 1]);
            xp1[k] = pack2(wbuf[(lane + 32) * XPAD + 2 * k],
                           wbuf[(lane + 32) * XPAD + 2 * k + 1]);
        }
        __syncwarp();   // wbuf reused for h/out staging below

#pragma unroll 1
        for (int hh = 0; hh < NH; hh++) {
            // [gate][batch] packed accumulators (halves = even/odd j sums)
            u64 a00 = 0, a01 = 0, a10 = 0, a11 = 0;
            u64 a20 = 0, a21 = 0, a30 = 0, a31 = 0;

            const u64* w0 = (const u64*)(sWih + (0 * NH + hh) * NI);
            const u64* w1 = (const u64*)(sWih + (1 * NH + hh) * NI);
            const u64* w2 = (const u64*)(sWih + (2 * NH + hh) * NI);
            const u64* w3 = (const u64*)(sWih + (3 * NH + hh) * NI);
#pragma unroll
            for (int q = 0; q < 9; q++) {            // 4 broadcast LDS.128
                ulonglong2 p0 = *(const ulonglong2*)(w0 + 2 * q);
                ulonglong2 p1 = *(const ulonglong2*)(w1 + 2 * q);
                ulonglong2 p2 = *(const ulonglong2*)(w2 + 2 * q);
                ulonglong2 p3 = *(const ulonglong2*)(w3 + 2 * q);
                u64 ua = xp0[2 * q], ub = xp0[2 * q + 1];
                u64 va = xp1[2 * q], vb = xp1[2 * q + 1];
                a00 = fma2(ua, p0.x, a00); a00 = fma2(ub, p0.y, a00);
                a01 = fma2(va, p0.x, a01); a01 = fma2(vb, p0.y, a01);
                a10 = fma2(ua, p1.x, a10); a10 = fma2(ub, p1.y, a10);
                a11 = fma2(va, p1.x, a11); a11 = fma2(vb, p1.y, a11);
                a20 = fma2(ua, p2.x, a20); a20 = fma2(ub, p2.y, a20);
                a21 = fma2(va, p2.x, a21); a21 = fma2(vb, p2.y, a21);
                a30 = fma2(ua, p3.x, a30); a30 = fma2(ub, p3.y, a30);
                a31 = fma2(va, p3.x, a31); a31 = fma2(vb, p3.y, a31);
            }

            const u64* v0 = (const u64*)(sWhh + (0 * NH + hh) * WPAD);
            const u64* v1 = (const u64*)(sWhh + (1 * NH + hh) * WPAD);
            const u64* v2 = (const u64*)(sWhh + (2 * NH + hh) * WPAD);
            const u64* v3 = (const u64*)(sWhh + (3 * NH + hh) * WPAD);
#pragma unroll
            for (int q = 0; q < 8; q++) {            // pads are 0
                ulonglong2 p0 = *(const ulonglong2*)(v0 + 2 * q);
                ulonglong2 p1 = *(const ulonglong2*)(v1 + 2 * q);
                ulonglong2 p2 = *(const ulonglong2*)(v2 + 2 * q);
                ulonglong2 p3 = *(const ulonglong2*)(v3 + 2 * q);
                u64 ua = hp0[2 * q], ub = hp0[2 * q + 1];
                u64 va = hp1[2 * q], vb = hp1[2 * q + 1];
                a00 = fma2(ua, p0.x, a00); a00 = fma2(ub, p0.y, a00);
                a01 = fma2(va, p0.x, a01); a01 = fma2(vb, p0.y, a01);
                a10 = fma2(ua, p1.x, a10); a10 = fma2(ub, p1.y, a10);
                a11 = fma2(va, p1.x, a11); a11 = fma2(vb, p1.y, a11);
                a20 = fma2(ua, p2.x, a20); a20 = fma2(ub, p2.y, a20);
                a21 = fma2(va, p2.x, a21); a21 = fma2(vb, p2.y, a21);
                a30 = fma2(ua, p3.x, a30); a30 = fma2(ub, p3.y, a30);
                a31 = fma2(va, p3.x, a31); a31 = fma2(vb, p3.y, a31);
            }

            float bi = sB[hh], bf = sB[NH + hh];
            float bg = sB[2 * NH + hh], bo = sB[3 * NH + hh];
            {
                float it = sigmoid_f(sum2(a00) + bi);
                float ft = sigmoid_f(sum2(a10) + bf);
                float gt = tanh_f(sum2(a20) + bg);
                float ot = sigmoid_f(sum2(a30) + bo);
                float cn = fmaf(ft, c0[hh], it * gt);
                c0[hh] = cn;
                wbuf[lane * XPAD + hh] = ot * tanh_f(cn);        // lane-private
            }
            {
                float it = sigmoid_f(sum2(a01) + bi);
                float ft = sigmoid_f(sum2(a11) + bf);
                float gt = tanh_f(sum2(a21) + bg);
                float ot = sigmoid_f(sum2(a31) + bo);
                float cn = fmaf(ft, c1[hh], it * gt);
                c1[hh] = cn;
                wbuf[(lane + 32) * XPAD + hh] = ot * tanh_f(cn);  // lane-private
            }
        }

        // repack h (j-pairs) for next step from lane-private rows
#pragma unroll
        for (int k = 0; k < NH / 2; k++) {
            hp0[k] = pack2(wbuf[lane * XPAD + 2 * k], wbuf[lane * XPAD + 2 * k + 1]);
            hp1[k] = pack2(wbuf[(lane + 32) * XPAD + 2 * k],
                           wbuf[(lane + 32) * XPAD + 2 * k + 1]);
        }
        hp0[15] = 0ull; hp1[15] = 0ull;   // pad pair stays zero
        __syncwarp();

        // ---- coalesced out store from wbuf ----
#pragma unroll
        for (int k = 0; k < 60; k++) {
            int i = lane + 32 * k;           // 64 rows * 30
            int r = i / 30;
            int c = i - r * 30;
            out[(size_t)(bbase + r) * (NT * NH) + t * NH + c] = wbuf[r * XPAD + c];
        }
        __syncwarp();                        // before next t restages x
    }

    // ---- final states ----
    float* hN = out + (size_t)NB * NT * NH;
    float* cN = hN + (size_t)NB * NH;
#pragma unroll
    for (int k = 0; k < NH / 2; k++) {
        float l0, h0f, l1, h1f;
        asm("mov.b64 {%0, %1}, %2;" : "=f"(l0), "=f"(h0f) : "l"(hp0[k]));
        asm("mov.b64 {%0, %1}, %2;" : "=f"(l1), "=f"(h1f) : "l"(hp1[k]));
        hN[(size_t)b0 * NH + 2 * k]     = l0;
        hN[(size_t)b0 * NH + 2 * k + 1] = h0f;
        hN[(size_t)b1 * NH + 2 * k]     = l1;
        hN[(size_t)b1 * NH + 2 * k + 1] = h1f;
    }
#pragma unroll
    for (int j = 0; j < NH; j++) {
        cN[(size_t)b0 * NH + j] = c0[j];
        cN[(size_t)b1 * NH + j] = c1[j];
    }
}

extern "C" void kernel_launch(void* const* d_in, const int* in_sizes, int n_in,
                              void* d_out, int out_size) {
    const float* x    = (const float*)d_in[0];
    const float* W_ih = (const float*)d_in[1];
    const float* W_hh = (const float*)d_in[2];
    const float* b_ih = (const float*)d_in[3];
    const float* b_hh = (const float*)d_in[4];
    float* out = (float*)d_out;

    cudaFuncSetAttribute(lstm_fused,
                         cudaFuncAttributeMaxDynamicSharedMemorySize, SMEM_BYTES);
    lstm_fused<<<GRID, BLOCK, SMEM_BYTES>>>(x, W_ih, W_hh, b_ih, b_hh, out);
}

// round 6
// speedup vs baseline: 2.2532x; 1.9773x over previous
#include <cuda_runtime.h>
#include <cstdint>

typedef unsigned int u32;

// LSTM B=65536, T=20, I=36, H=30. Gate order i,f,g,o.
// Output: out[B,T,H] ++ h_n[1,B,H] ++ c_n[1,B,H], fp32.
//
// mma.sync m16n8k16 bf16 (sm_80 baseline PTX -> works on compute_103 target).
// Per warp: 16 batches, full recurrence, no CTA-level sync in the t-loop.
// K=80 = [x 0..35 | h 36..65 | bias 66 | zeros]; N=120, n = hh*4 + gate.
// 3-pass bf16 hi/lo compensation => fp32-quality gates.

#define NB   65536
#define NT   20
#define NIn  36
#define NH   30

#define BLOCK 128                 // 4 warps, 64 batches per CTA
#define GRID  (NB / 64)           // 1024

#define PITCH 84                  // per-warp A-slab row pitch (floats)
#define SLAB_FLOATS (16 * PITCH)  // 1344
#define NCHUNK 5                  // K = 80 = 5 x 16
#define NTILE  15                 // N = 120 = 15 x 8

#define B_ENTRIES (NCHUNK * NTILE * 32)       // 2400 uint4
#define OFF_SLAB  (B_ENTRIES * 16)            // 38400 bytes
#define SMEM_BYTES (OFF_SLAB + 4 * SLAB_FLOATS * 4)   // 59904

// round-to-nearest bf16 "hi" part, kept as fp32 bit pattern (low 16 = 0)
__device__ __forceinline__ u32 bf16hi_u(float v) {
    return (__float_as_uint(v) + 0x8000u) & 0xFFFF0000u;
}
// pack two hi parts (given as fp32 bit patterns) -> bf16x2 {lo=even, hi=odd}
__device__ __forceinline__ u32 prmt_pack(u32 even_hi, u32 odd_hi) {
    u32 d;
    asm("prmt.b32 %0, %1, %2, 0x7632;" : "=r"(d) : "r"(even_hi), "r"(odd_hi));
    return d;
}
// round-convert two floats -> bf16x2 {lo=even, hi=odd}
__device__ __forceinline__ u32 bf16x2_rn(float even, float odd) {
    u32 d;
    asm("cvt.rn.bf16x2.f32 %0, %1, %2;" : "=r"(d) : "f"(odd), "f"(even));
    return d;
}

__device__ __forceinline__ void mma_bf16(float* d, u32 a0, u32 a1, u32 a2, u32 a3,
                                         u32 b0, u32 b1) {
    asm volatile(
        "mma.sync.aligned.m16n8k16.row.col.f32.bf16.bf16.f32 "
        "{%0,%1,%2,%3}, {%4,%5,%6,%7}, {%8,%9}, {%0,%1,%2,%3};"
        : "+f"(d[0]), "+f"(d[1]), "+f"(d[2]), "+f"(d[3])
        : "r"(a0), "r"(a1), "r"(a2), "r"(a3), "r"(b0), "r"(b1));
}

// A-frag pair build: f32 pair -> (hi bf16x2, lo bf16x2)
__device__ __forceinline__ void mk_ahl(float2 f, u32& hi, u32& lo) {
    u32 he = bf16hi_u(f.x), ho = bf16hi_u(f.y);
    hi = prmt_pack(he, ho);
    lo = bf16x2_rn(f.x - __uint_as_float(he), f.y - __uint_as_float(ho));
}

__device__ __forceinline__ float sigmoid_f(float v) {
    return __fdividef(1.0f, 1.0f + __expf(-v));
}
__device__ __forceinline__ float tanh_f(float v) {
    return __fdividef(2.0f, 1.0f + __expf(-2.0f * v)) - 1.0f;
}

// concatenated weight matrix: row n (gate-interleaved), col k in [0,80)
__device__ __forceinline__ float wcat(int n, int k,
                                      const float* W_ih, const float* W_hh,
                                      const float* b_ih, const float* b_hh) {
    int g = n & 3, hh = n >> 2;
    int row = g * NH + hh;
    if (k < 36) return W_ih[row * NIn + k];
    if (k < 66) return W_hh[row * NH + (k - 36)];
    if (k == 66) return b_ih[row] + b_hh[row];
    return 0.0f;
}

__global__ void __launch_bounds__(BLOCK, 3)
lstm_hmma(const float* __restrict__ x,
          const float* __restrict__ W_ih,
          const float* __restrict__ W_hh,
          const float* __restrict__ b_ih,
          const float* __restrict__ b_hh,
          float* __restrict__ out) {
    extern __shared__ __align__(16) char smraw[];
    uint4* Bs   = reinterpret_cast<uint4*>(smraw);
    float* slab = reinterpret_cast<float*>(smraw + OFF_SLAB) + (threadIdx.x >> 5) * SLAB_FLOATS;

    const int tid  = threadIdx.x;
    const int wid  = tid >> 5;
    const int lane = tid & 31;
    const int wB   = blockIdx.x * 64 + wid * 16;   // warp's first batch

    // ---- one-time B fragment prep (hi/lo bf16x2, per-lane layout) ----
    for (int idx = tid; idx < B_ENTRIES; idx += BLOCK) {
        int ch  = idx / (NTILE * 32);
        int rem = idx - ch * NTILE * 32;
        int j   = rem >> 5, ln = rem & 31;
        int n   = j * 8 + (ln >> 2);
        int kb  = 16 * ch + 2 * (ln & 3);
        float w00 = wcat(n, kb,     W_ih, W_hh, b_ih, b_hh);
        float w01 = wcat(n, kb + 1, W_ih, W_hh, b_ih, b_hh);
        float w10 = wcat(n, kb + 8, W_ih, W_hh, b_ih, b_hh);
        float w11 = wcat(n, kb + 9, W_ih, W_hh, b_ih, b_hh);
        u32 h00 = bf16hi_u(w00), h01 = bf16hi_u(w01);
        u32 h10 = bf16hi_u(w10), h11 = bf16hi_u(w11);
        uint4 e;
        e.x = prmt_pack(h00, h01);
        e.y = prmt_pack(h10, h11);
        e.z = bf16x2_rn(w00 - __uint_as_float(h00), w01 - __uint_as_float(h01));
        e.w = bf16x2_rn(w10 - __uint_as_float(h10), w11 - __uint_as_float(h11));
        Bs[idx] = e;
    }

    // ---- per-warp A slab init: zeros, bias column 66 = 1 ----
    for (int i = lane; i < SLAB_FLOATS; i += 32) slab[i] = 0.0f;
    __syncwarp();
    if (lane < 16) slab[lane * PITCH + 66] = 1.0f;
    __syncthreads();

    const float4* xg = reinterpret_cast<const float4*>(x);

    // preload x(t=0) fragments (coalesced float4, 16 rows x 9 quads)
    float4 xr[5];
#pragma unroll
    for (int k = 0; k < 5; k++) {
        int i = lane + 32 * k;
        if (i < 144) {
            int rr = i / 9, q = i - rr * 9;
            xr[k] = xg[(size_t)(wB + rr) * (NT * NIn / 4) + q];
        }
    }

    const int r  = lane >> 2;                 // frag row 0..7
    const bool ev = (lane & 1) == 0;
    const int rowp = r + (ev ? 0 : 8);        // this lane's cell row
    const int hsel = (lane >> 1) & 1;         // hh = 2j + hsel

    float creg[NTILE];
#pragma unroll
    for (int j = 0; j < NTILE; j++) creg[j] = 0.0f;

    for (int t = 0; t < NT; t++) {
        // ---- stage x into slab cols 0..35 ----
#pragma unroll
        for (int k = 0; k < 5; k++) {
            int i = lane + 32 * k;
            if (i < 144) {
                int rr = i / 9, q = i - rr * 9;
                *reinterpret_cast<float4*>(slab + rr * PITCH + 4 * q) = xr[k];
            }
        }
        __syncwarp();

        // prefetch x(t+1) early (latency hidden under the MMA loop)
        if (t < NT - 1) {
#pragma unroll
            for (int k = 0; k < 5; k++) {
                int i = lane + 32 * k;
                if (i < 144) {
                    int rr = i / 9, q = i - rr * 9;
                    xr[k] = xg[(size_t)(wB + rr) * (NT * NIn / 4) + (t + 1) * 9 + q];
                }
            }
        }

        // ---- GEMM: D[16 x 120] over K=80, 3-pass hi/lo ----
        float D[4 * NTILE];
#pragma unroll
        for (int i = 0; i < 4 * NTILE; i++) D[i] = 0.0f;

#pragma unroll
        for (int ch = 0; ch < NCHUNK; ch++) {
            int kb = 16 * ch + 2 * (lane & 3);
            u32 ah0, al0, ah1, al1, ah2, al2, ah3, al3;
            mk_ahl(*reinterpret_cast<const float2*>(slab + r * PITCH + kb),           ah0, al0);
            mk_ahl(*reinterpret_cast<const float2*>(slab + (r + 8) * PITCH + kb),     ah1, al1);
            mk_ahl(*reinterpret_cast<const float2*>(slab + r * PITCH + kb + 8),       ah2, al2);
            mk_ahl(*reinterpret_cast<const float2*>(slab + (r + 8) * PITCH + kb + 8), ah3, al3);
#pragma unroll
            for (int j = 0; j < NTILE; j++) {
                uint4 B = Bs[(ch * NTILE + j) * 32 + lane];
                mma_bf16(D + 4 * j, ah0, ah1, ah2, ah3, B.x, B.y);  // Ahi*Bhi
                mma_bf16(D + 4 * j, al0, al1, al2, al3, B.x, B.y);  // Alo*Bhi
                mma_bf16(D + 4 * j, ah0, ah1, ah2, ah3, B.z, B.w);  // Ahi*Blo
            }
        }

        // ---- epilogue: 1 cell per lane per ntile ----
#pragma unroll
        for (int j = 0; j < NTILE; j++) {
            float d0 = D[4 * j], d1 = D[4 * j + 1], d2 = D[4 * j + 2], d3 = D[4 * j + 3];
            float e0 = __shfl_xor_sync(0xffffffffu, d0, 1);
            float e1 = __shfl_xor_sync(0xffffffffu, d1, 1);
            float e2 = __shfl_xor_sync(0xffffffffu, d2, 1);
            float e3 = __shfl_xor_sync(0xffffffffu, d3, 1);
            float gi = ev ? d0 : e2;
            float gf = ev ? d1 : e3;
            float gg = ev ? e0 : d2;
            float go = ev ? e1 : d3;
            float it = sigmoid_f(gi), ft = sigmoid_f(gf);
            float gt = tanh_f(gg),    ot = sigmoid_f(go);
            float cn = fmaf(ft, creg[j], it * gt);
            creg[j] = cn;
            slab[rowp * PITCH + 36 + (2 * j + hsel)] = ot * tanh_f(cn);
        }
        __syncwarp();

        // ---- coalesced-ish out write: 16 rows x 30 from slab h cols ----
#pragma unroll
        for (int k = 0; k < 15; k++) {
            int i = lane + 32 * k;                  // < 480
            int rr = i / 30, cc = i - rr * 30;
            out[(size_t)(wB + rr) * (NT * NH) + t * NH + cc] =
                slab[rr * PITCH + 36 + cc];
        }
        __syncwarp();   // before next t overwrites slab x / reads h
    }

    // ---- final states ----
    float* hN = out + (size_t)NB * NT * NH;
    float* cN = hN + (size_t)NB * NH;
#pragma unroll
    for (int k = 0; k < 15; k++) {
        int i = lane + 32 * k;
        int rr = i / 30, cc = i - rr * 30;
        hN[(size_t)(wB + rr) * NH + cc] = slab[rr * PITCH + 36 + cc];
    }
    __syncwarp();
#pragma unroll
    for (int j = 0; j < NTILE; j++)
        slab[rowp * PITCH + 36 + (2 * j + hsel)] = creg[j];
    __syncwarp();
#pragma unroll
    for (int k = 0; k < 15; k++) {
        int i = lane + 32 * k;
        int rr = i / 30, cc = i - rr * 30;
        cN[(size_t)(wB + rr) * NH + cc] = slab[rr * PITCH + 36 + cc];
    }
}

extern "C" void kernel_launch(void* const* d_in, const int* in_sizes, int n_in,
                              void* d_out, int out_size) {
    const float* x    = (const float*)d_in[0];
    const float* W_ih = (const float*)d_in[1];
    const float* W_hh = (const float*)d_in[2];
    const float* b_ih = (const float*)d_in[3];
    const float* b_hh = (const float*)d_in[4];
    float* out = (float*)d_out;

    cudaFuncSetAttribute(lstm_hmma,
                         cudaFuncAttributeMaxDynamicSharedMemorySize, SMEM_BYTES);
    lstm_hmma<<<GRID, BLOCK, SMEM_BYTES>>>(x, W_ih, W_hh, b_ih, b_hh, out);
}

// round 7
// speedup vs baseline: 2.5685x; 1.1400x over previous
#include <cuda_runtime.h>
#include <cstdint>

typedef unsigned int u32;

// LSTM B=65536, T=20, I=36, H=30. Gate order i,f,g,o.
// Output: out[B,T,H] ++ h_n[1,B,H] ++ c_n[1,B,H], fp32.
//
// mma.sync m16n8k16 bf16, 3-pass hi/lo compensation (fp32-quality gates).
// M=32 per warp (2 m16 tiles): each B-fragment LDS.128 feeds 6 MMAs,
// halving L1 traffic per unit work and doubling per-warp MMA ILP.
// x prefetched via cp.async into the per-warp slab (no prefetch registers).

#define NB   65536
#define NT   20
#define NIn  36
#define NH   30

#define BLOCK 128                 // 4 warps, 128 batches per CTA
#define GRID  (NB / 128)          // 512

#define PITCH 84                  // per-warp A-slab row pitch (floats)
#define SLAB_FLOATS (32 * PITCH)  // 2688
#define NCHUNK 5                  // K = 80 = 5 x 16 : [x36 | h30 | bias | 0pad]
#define NTILE  15                 // N = 120 = 15 x 8, n = hh*4 + gate

#define B_ENTRIES (NCHUNK * NTILE * 32)       // 2400 uint4
#define OFF_SLAB  (B_ENTRIES * 16)            // 38400 bytes
#define SMEM_BYTES (OFF_SLAB + 4 * SLAB_FLOATS * 4)   // 81408

__device__ __forceinline__ u32 bf16hi_u(float v) {
    return (__float_as_uint(v) + 0x8000u) & 0xFFFF0000u;
}
__device__ __forceinline__ u32 prmt_pack(u32 even_hi, u32 odd_hi) {
    u32 d;
    asm("prmt.b32 %0, %1, %2, 0x7632;" : "=r"(d) : "r"(even_hi), "r"(odd_hi));
    return d;
}
__device__ __forceinline__ u32 bf16x2_rn(float even, float odd) {
    u32 d;
    asm("cvt.rn.bf16x2.f32 %0, %1, %2;" : "=r"(d) : "f"(odd), "f"(even));
    return d;
}
__device__ __forceinline__ void mma_bf16(float* d, u32 a0, u32 a1, u32 a2, u32 a3,
                                         u32 b0, u32 b1) {
    asm volatile(
        "mma.sync.aligned.m16n8k16.row.col.f32.bf16.bf16.f32 "
        "{%0,%1,%2,%3}, {%4,%5,%6,%7}, {%8,%9}, {%0,%1,%2,%3};"
        : "+f"(d[0]), "+f"(d[1]), "+f"(d[2]), "+f"(d[3])
        : "r"(a0), "r"(a1), "r"(a2), "r"(a3), "r"(b0), "r"(b1));
}
__device__ __forceinline__ void mk_ahl(float2 f, u32& hi, u32& lo) {
    u32 he = bf16hi_u(f.x), ho = bf16hi_u(f.y);
    hi = prmt_pack(he, ho);
    lo = bf16x2_rn(f.x - __uint_as_float(he), f.y - __uint_as_float(ho));
}

__device__ __forceinline__ float sigmoid_f(float v) {
    return __fdividef(1.0f, 1.0f + __expf(-v));
}
__device__ __forceinline__ float tanh_f(float v) {
    return __fdividef(2.0f, 1.0f + __expf(-2.0f * v)) - 1.0f;
}

__device__ __forceinline__ u32 s2u(const void* p) {
    u32 a;
    asm("{ .reg .u64 t; cvta.to.shared.u64 t, %1; cvt.u32.u64 %0, t; }"
        : "=r"(a) : "l"(p));
    return a;
}
#define CP16(dst, src) \
    asm volatile("cp.async.ca.shared.global [%0], [%1], 16;" :: "r"(dst), "l"(src))
#define CP_COMMIT() asm volatile("cp.async.commit_group;" ::: "memory")
#define CP_WAIT0()  asm volatile("cp.async.wait_group 0;" ::: "memory")

// concatenated weight matrix: row n (gate-interleaved), col k in [0,80)
__device__ __forceinline__ float wcat(int n, int k,
                                      const float* W_ih, const float* W_hh,
                                      const float* b_ih, const float* b_hh) {
    int g = n & 3, hh = n >> 2;
    int row = g * NH + hh;
    if (k < 36) return W_ih[row * NIn + k];
    if (k < 66) return W_hh[row * NH + (k - 36)];
    if (k == 66) return b_ih[row] + b_hh[row];
    return 0.0f;
}

__global__ void __launch_bounds__(BLOCK, 2)
lstm_hmma32(const float* __restrict__ x,
            const float* __restrict__ W_ih,
            const float* __restrict__ W_hh,
            const float* __restrict__ b_ih,
            const float* __restrict__ b_hh,
            float* __restrict__ out) {
    extern __shared__ __align__(16) char smraw[];
    uint4* Bs   = reinterpret_cast<uint4*>(smraw);
    float* slab = reinterpret_cast<float*>(smraw + OFF_SLAB) + (threadIdx.x >> 5) * SLAB_FLOATS;

    const int tid  = threadIdx.x;
    const int lane = tid & 31;
    const int wB   = blockIdx.x * 128 + (tid >> 5) * 32;   // warp's first batch
    const u32 slab_u = s2u(slab);

    // ---- one-time B fragment prep (hi/lo bf16x2, per-lane layout) ----
    for (int idx = tid; idx < B_ENTRIES; idx += BLOCK) {
        int ch  = idx / (NTILE * 32);
        int rem = idx - ch * NTILE * 32;
        int j   = rem >> 5, ln = rem & 31;
        int n   = j * 8 + (ln >> 2);
        int kb  = 16 * ch + 2 * (ln & 3);
        float w00 = wcat(n, kb,     W_ih, W_hh, b_ih, b_hh);
        float w01 = wcat(n, kb + 1, W_ih, W_hh, b_ih, b_hh);
        float w10 = wcat(n, kb + 8, W_ih, W_hh, b_ih, b_hh);
        float w11 = wcat(n, kb + 9, W_ih, W_hh, b_ih, b_hh);
        u32 h00 = bf16hi_u(w00), h01 = bf16hi_u(w01);
        u32 h10 = bf16hi_u(w10), h11 = bf16hi_u(w11);
        uint4 e;
        e.x = prmt_pack(h00, h01);
        e.y = prmt_pack(h10, h11);
        e.z = bf16x2_rn(w00 - __uint_as_float(h00), w01 - __uint_as_float(h01));
        e.w = bf16x2_rn(w10 - __uint_as_float(h10), w11 - __uint_as_float(h11));
        Bs[idx] = e;
    }

    // ---- per-warp slab init: zeros, bias column 66 = 1 ----
#pragma unroll
    for (int i = lane; i < SLAB_FLOATS / 4; i += 32)
        *reinterpret_cast<float4*>(slab + 4 * i) = make_float4(0, 0, 0, 0);
    __syncwarp();
    slab[lane * PITCH + 66] = 1.0f;     // 32 rows, one per lane
    __syncthreads();

    // ---- prefetch x(t=0) into slab via cp.async (9 quads/lane, exact) ----
#pragma unroll
    for (int k = 0; k < 9; k++) {
        int i = lane + 32 * k;          // 0..287 = 32 rows * 9 quads
        int rr = i / 9, q = i - rr * 9;
        CP16(slab_u + (rr * PITCH + 4 * q) * 4,
             x + (size_t)(wB + rr) * (NT * NIn) + 4 * q);
    }
    CP_COMMIT();

    const int r    = lane >> 2;               // frag row 0..7
    const bool ev  = (lane & 1) == 0;
    const int rowp = r + (ev ? 0 : 8);        // m0 cell row; m1 = rowp+16
    const int hsel = (lane >> 1) & 1;         // hh = 2j + hsel

    float c0[NTILE], c1[NTILE];
#pragma unroll
    for (int j = 0; j < NTILE; j++) { c0[j] = 0.0f; c1[j] = 0.0f; }

    for (int t = 0; t < NT; t++) {
        CP_WAIT0();
        __syncwarp();                         // x(t) and h(t) visible warp-wide

        // ---- GEMM: D[32 x 120] over K=80, 3-pass hi/lo ----
        float D[8 * NTILE];                   // m0: 0..59, m1: 60..119
#pragma unroll
        for (int i = 0; i < 8 * NTILE; i++) D[i] = 0.0f;

#pragma unroll
        for (int ch = 0; ch < NCHUNK; ch++) {
            int kb = 16 * ch + 2 * (lane & 3);
            u32 p0h, p0l, p1h, p1l, p2h, p2l, p3h, p3l;   // m0 frags
            u32 q0h, q0l, q1h, q1l, q2h, q2l, q3h, q3l;   // m1 frags
            mk_ahl(*reinterpret_cast<const float2*>(slab + r * PITCH + kb),            p0h, p0l);
            mk_ahl(*reinterpret_cast<const float2*>(slab + (r + 8) * PITCH + kb),      p1h, p1l);
            mk_ahl(*reinterpret_cast<const float2*>(slab + r * PITCH + kb + 8),        p2h, p2l);
            mk_ahl(*reinterpret_cast<const float2*>(slab + (r + 8) * PITCH + kb + 8),  p3h, p3l);
            mk_ahl(*reinterpret_cast<const float2*>(slab + (r + 16) * PITCH + kb),     q0h, q0l);
            mk_ahl(*reinterpret_cast<const float2*>(slab + (r + 24) * PITCH + kb),     q1h, q1l);
            mk_ahl(*reinterpret_cast<const float2*>(slab + (r + 16) * PITCH + kb + 8), q2h, q2l);
            mk_ahl(*reinterpret_cast<const float2*>(slab + (r + 24) * PITCH + kb + 8), q3h, q3l);
#pragma unroll
            for (int j = 0; j < NTILE; j++) {
                uint4 B = Bs[(ch * NTILE + j) * 32 + lane];
                mma_bf16(D + 4 * j,      p0h, p1h, p2h, p3h, B.x, B.y);  // m0 hi*hi
                mma_bf16(D + 60 + 4 * j, q0h, q1h, q2h, q3h, B.x, B.y);  // m1 hi*hi
                mma_bf16(D + 4 * j,      p0l, p1l, p2l, p3l, B.x, B.y);  // m0 lo*hi
                mma_bf16(D + 60 + 4 * j, q0l, q1l, q2l, q3l, B.x, B.y);  // m1 lo*hi
                mma_bf16(D + 4 * j,      p0h, p1h, p2h, p3h, B.z, B.w);  // m0 hi*lo
                mma_bf16(D + 60 + 4 * j, q0h, q1h, q2h, q3h, B.z, B.w);  // m1 hi*lo
            }
        }

        // ---- prefetch x(t+1) (slab x-cols free to overwrite now) ----
        if (t < NT - 1) {
#pragma unroll
            for (int k = 0; k < 9; k++) {
                int i = lane + 32 * k;
                int rr = i / 9, q = i - rr * 9;
                CP16(slab_u + (rr * PITCH + 4 * q) * 4,
                     x + (size_t)(wB + rr) * (NT * NIn) + (t + 1) * NIn + 4 * q);
            }
            CP_COMMIT();
        }

        // ---- epilogue: 2 cells per lane per ntile (m0, m1) ----
#pragma unroll
        for (int j = 0; j < NTILE; j++) {
#pragma unroll
            for (int m = 0; m < 2; m++) {
                float* Dm = D + 60 * m + 4 * j;
                float d0 = Dm[0], d1 = Dm[1], d2 = Dm[2], d3 = Dm[3];
                float e0 = __shfl_xor_sync(0xffffffffu, d0, 1);
                float e1 = __shfl_xor_sync(0xffffffffu, d1, 1);
                float e2 = __shfl_xor_sync(0xffffffffu, d2, 1);
                float e3 = __shfl_xor_sync(0xffffffffu, d3, 1);
                float gi = ev ? d0 : e2;
                float gf = ev ? d1 : e3;
                float gg = ev ? e0 : d2;
                float go = ev ? e1 : d3;
                float it = sigmoid_f(gi), ft = sigmoid_f(gf);
                float gt = tanh_f(gg),    ot = sigmoid_f(go);
                float* cr = m ? c1 : c0;
                float cn = fmaf(ft, cr[j], it * gt);
                cr[j] = cn;
                slab[(rowp + 16 * m) * PITCH + 36 + (2 * j + hsel)] = ot * tanh_f(cn);
            }
        }
        __syncwarp();

        // ---- out write: 32 rows x 30 from slab h cols ----
#pragma unroll
        for (int k = 0; k < 30; k++) {
            int i = lane + 32 * k;                  // < 960
            int rr = i / 30, cc = i - rr * 30;
            out[(size_t)(wB + rr) * (NT * NH) + t * NH + cc] =
                slab[rr * PITCH + 36 + cc];
        }
        __syncwarp();   // h reads done before next epilogue overwrites
    }

    // ---- final states ----
    float* hN = out + (size_t)NB * NT * NH;
    float* cN = hN + (size_t)NB * NH;
#pragma unroll
    for (int k = 0; k < 30; k++) {
        int i = lane + 32 * k;
        int rr = i / 30, cc = i - rr * 30;
        hN[(size_t)(wB + rr) * NH + cc] = slab[rr * PITCH + 36 + cc];
    }
    __syncwarp();
#pragma unroll
    for (int j = 0; j < NTILE; j++) {
        slab[rowp * PITCH + 36 + (2 * j + hsel)]        = c0[j];
        slab[(rowp + 16) * PITCH + 36 + (2 * j + hsel)] = c1[j];
    }
    __syncwarp();
#pragma unroll
    for (int k = 0; k < 30; k++) {
        int i = lane + 32 * k;
        int rr = i / 30, cc = i - rr * 30;
        cN[(size_t)(wB + rr) * NH + cc] = slab[rr * PITCH + 36 + cc];
    }
}

extern "C" void kernel_launch(void* const* d_in, const int* in_sizes, int n_in,
                              void* d_out, int out_size) {
    const float* x    = (const float*)d_in[0];
    const float* W_ih = (const float*)d_in[1];
    const float* W_hh = (const float*)d_in[2];
    const float* b_ih = (const float*)d_in[3];
    const float* b_hh = (const float*)d_in[4];
    float* out = (float*)d_out;

    cudaFuncSetAttribute(lstm_hmma32,
                         cudaFuncAttributeMaxDynamicSharedMemorySize, SMEM_BYTES);
    lstm_hmma32<<<GRID, BLOCK, SMEM_BYTES>>>(x, W_ih, W_hh, b_ih, b_hh, out);
}